// round 13
// baseline (speedup 1.0000x reference)
#include <cuda_runtime.h>
#include <cstdint>

// Problem constants
#define BQ   2
#define NQ   6
#define CQ   3
#define HQ   64
#define WQ   176
#define DQ   64
#define HWQ  (HQ * WQ)        // 11264
#define BN   (BQ * NQ)        // 12
#define ROWS (BN * CQ)        // 36
#define CHUNKS 8              // partial-sum chunks per row
#define NPROD (ROWS * CHUNKS) // 288 producer blocks
#define F4_PER_CHUNK ((HWQ / 4) / CHUNKS)   // 352

#define TILE_PX 64
#define GRIDX  (HWQ / TILE_PX)   // 176
#define NBLOCKS (GRIDX * BN)     // 2112

// Scratch (no device allocs allowed)
__device__ float    g_partial[ROWS][CHUNKS];
__device__ unsigned g_ready;   // producers done counter (self-resetting)
__device__ unsigned g_done;    // consumers past-wait counter (self-resetting)

// ---------------------------------------------------------------------------
// Single fused kernel, 2112 blocks of 256 threads (8/SM -> wave-1 = ~1184
// blocks, deterministically the lowest bids, so all 288 producers are
// resident in wave 1 -> flag-wait cannot deadlock).
//
//  1. preamble (independent): tile feat loads + exp, K^{-1}, extrinsics
//  2. bid<288: compute one (row,chunk) partial sum(exp); publish; count up
//  3. all: wait g_ready==288; reduce 8 partials/row via __ldcg (fixed order)
//  4. per-pixel scalars s_i; coalesced float4 store phase (R2/R7 structure)
//  5. g_done epilogue resets counters for graph replay
// ---------------------------------------------------------------------------
__global__ __launch_bounds__(256) void lss_fused_kernel(
    const float* __restrict__ feat,      // (BN, C, HW)
    const float* __restrict__ intr,      // (B, N, 4, 4)
    const float* __restrict__ extr,      // (B, N, 4, 4)
    const float* __restrict__ depths,    // (D)
    float* __restrict__ out)             // (BN, 3, HW, D)
{
    const int tid = threadIdx.x;
    const int bn  = blockIdx.y;
    const int p0  = blockIdx.x * TILE_PX;
    const int bid = blockIdx.x + blockIdx.y * GRIDX;

    __shared__ float sS[3][TILE_PX];
    __shared__ float sE[12];
    __shared__ float sK[9];
    __shared__ float sInv[3];
    __shared__ float swp[8];             // producer reduce scratch

    // ---- 1. Independent preamble ----
    float e0 = 0.f, e1 = 0.f, e2 = 0.f, x = 0.f, y = 0.f;
    if (tid < TILE_PX) {
        const int p = p0 + tid;
        x = (float)(p % WQ);
        y = (float)(p / WQ);
        const size_t fbase = (size_t)bn * CQ * HWQ + p;
        e0 = __expf(feat[fbase          ]);
        e1 = __expf(feat[fbase +     HWQ]);
        e2 = __expf(feat[fbase + 2 * HWQ]);
    }
    if (tid < 12) sE[tid] = extr[bn * 16 + tid];
    if (tid == 128) {                    // K^{-1} by adjugate, one spare thread
        const float* A = intr + bn * 16;
        float a = A[0], b = A[1], c = A[2];
        float d = A[4], e = A[5], f = A[6];
        float g = A[8], h = A[9], i = A[10];
        float det = a * (e * i - f * h) - b * (d * i - f * g) + c * (d * h - e * g);
        float id  = 1.0f / det;
        sK[0] = (e * i - f * h) * id;  sK[1] = (c * h - b * i) * id;  sK[2] = (b * f - c * e) * id;
        sK[3] = (f * g - d * i) * id;  sK[4] = (a * i - c * g) * id;  sK[5] = (c * d - a * f) * id;
        sK[6] = (d * h - e * g) * id;  sK[7] = (b * g - a * h) * id;  sK[8] = (a * e - b * d) * id;
    }

    const int q   = tid & 15;            // depth-quad index, fixed per thread
    const int wpl = tid >> 4;            // pixel sub-index 0..15
    const float4 dep = reinterpret_cast<const float4*>(depths)[q];

    // ---- 2. Producer blocks: one (row, chunk) partial sum of exp ----
    if (bid < NPROD) {
        const int row   = bid >> 3;      // 0..35
        const int chunk = bid & 7;       // 0..7
        const float4* f4 = reinterpret_cast<const float4*>(
            feat + (size_t)row * HWQ) + chunk * F4_PER_CHUNK;
        float sum = 0.0f;
        for (int i2 = tid; i2 < F4_PER_CHUNK; i2 += 256) {
            const float4 v = f4[i2];
            sum += __expf(v.x) + __expf(v.y) + __expf(v.z) + __expf(v.w);
        }
        #pragma unroll
        for (int o = 16; o > 0; o >>= 1) sum += __shfl_xor_sync(0xFFFFFFFFu, sum, o);
        if ((tid & 31) == 0) swp[tid >> 5] = sum;
        __syncthreads();
        if (tid == 0) {
            float t = 0.0f;
            #pragma unroll
            for (int w = 0; w < 8; w++) t += swp[w];
            g_partial[row][chunk] = t;
            __threadfence();                     // release partial
            atomicAdd(&g_ready, 1u);
        }
    }

    // ---- 3. Wait for all 288 partials, then reduce (deterministic order) ----
    if (tid == 0) {
        while (*((volatile unsigned*)&g_ready) < (unsigned)NPROD) { __nanosleep(32); }
        __threadfence();                         // acquire partials
    }
    __syncthreads();

    if (tid < 24) {                              // 3 rows x 8 chunks, shfl 8-groups
        const int r = tid >> 3, ch = tid & 7;
        float v = __ldcg(&g_partial[bn * CQ + r][ch]);   // L2 read, skip stale L1
        v += __shfl_xor_sync(0x00FFFFFFu, v, 4);
        v += __shfl_xor_sync(0x00FFFFFFu, v, 2);
        v += __shfl_xor_sync(0x00FFFFFFu, v, 1);
        if (ch == 0) sInv[r] = 1.0f / v;
    }
    __syncthreads();

    // ---- 4a. Per-pixel scalars ----
    if (tid < TILE_PX) {
        const float t0 = e0 * sInv[0] * fmaf(sK[0], x, fmaf(sK[1], y, sK[2]));
        const float t1 = e1 * sInv[1] * fmaf(sK[3], x, fmaf(sK[4], y, sK[5]));
        const float t2 = e2 * sInv[2] * fmaf(sK[6], x, fmaf(sK[7], y, sK[8]));
        #pragma unroll
        for (int i = 0; i < 3; i++)
            sS[i][tid] = fmaf(sE[i * 4 + 0], t0,
                         fmaf(sE[i * 4 + 1], t1,
                              sE[i * 4 + 2] * t2));
    }
    __syncthreads();

    // ---- 4b. Store phase: q fixed per thread -> 512B contiguous warp spans ----
    float4* out4 = reinterpret_cast<float4*>(out);
    #pragma unroll
    for (int i = 0; i < 3; i++) {
        const float e3 = sE[i * 4 + 3];
        const size_t base = ((size_t)(bn * 3 + i) * HWQ + p0) * (DQ / 4) + q;
        #pragma unroll
        for (int r = 0; r < 4; r++) {
            const int pl = r * 16 + wpl;
            const float s = sS[i][pl];
            float4 o;
            o.x = fmaf(s, dep.x, e3);
            o.y = fmaf(s, dep.y, e3);
            o.z = fmaf(s, dep.z, e3);
            o.w = fmaf(s, dep.w, e3);
            out4[base + (size_t)pl * (DQ / 4)] = o;
        }
    }

    // ---- 5. Epilogue: last block past this point resets counters ----
    if (tid == 0) {
        const unsigned d = atomicAdd(&g_done, 1u);
        if (d == (unsigned)(NBLOCKS - 1)) {      // everyone passed the wait
            *((volatile unsigned*)&g_ready) = 0u;
            *((volatile unsigned*)&g_done)  = 0u;
        }
    }
}

extern "C" void kernel_launch(void* const* d_in, const int* in_sizes, int n_in,
                              void* d_out, int out_size)
{
    const float* feat   = (const float*)d_in[0];  // image_features (BN,C,H,W)
    const float* intr   = (const float*)d_in[1];  // intrinsics (B,N,4,4)
    const float* extr   = (const float*)d_in[2];  // extrinsics (B,N,4,4)
    // d_in[3] = xy1 (unused: x,y recomputed exactly from pixel index)
    const float* depths = (const float*)d_in[4];  // (D)
    float* out = (float*)d_out;

    dim3 grid(GRIDX, BN);
    lss_fused_kernel<<<grid, 256>>>(feat, intr, extr, depths, out);
}

// round 14
// speedup vs baseline: 1.2186x; 1.2186x over previous
#include <cuda_runtime.h>
#include <cstdint>

// Problem constants
#define BQ   2
#define NQ   6
#define CQ   3
#define HQ   64
#define WQ   176
#define DQ   64
#define HWQ  (HQ * WQ)        // 11264
#define BN   (BQ * NQ)        // 12
#define ROWS (BN * CQ)        // 36
#define CHUNKS 11             // partial-sum chunks per row
#define F4_PER_CHUNK ((HWQ / 4) / CHUNKS)   // 256  (exactly 1 float4/thread)

// Scratch (no device allocs allowed)
__device__ float g_partial[ROWS][CHUNKS];
__device__ float g_kinv[BN][9];

// ---------------------------------------------------------------------------
// Kernel 1 (producer): minimum-latency partial sum of exp per (row, chunk).
// grid=(CHUNKS, ROWS)=396 blocks x 256 threads: ONE float4 load + 4 exp per
// thread, then a 2-level reduce. Signals PDL dependents at entry.
// No max-shift: inputs ~N(0,1), fp32 exp is safe.
// ---------------------------------------------------------------------------
__global__ __launch_bounds__(256) void lss_stats_kernel(
    const float* __restrict__ feat,      // (BN, C, HW)
    const float* __restrict__ intr)      // (B, N, 4, 4)
{
    if (threadIdx.x == 0)
        asm volatile("griddepcontrol.launch_dependents;" ::: "memory");

    const int chunk = blockIdx.x;        // 0..10
    const int row   = blockIdx.y;        // 0..35
    const int tid   = threadIdx.x;

    if (chunk == 0 && (row % CQ) == 0 && tid == 0) {
        const int bn = row / CQ;
        const float* A = intr + bn * 16;
        float a = A[0], b = A[1], c = A[2];
        float d = A[4], e = A[5], f = A[6];
        float g = A[8], h = A[9], i = A[10];
        float det = a * (e * i - f * h) - b * (d * i - f * g) + c * (d * h - e * g);
        float id  = 1.0f / det;
        float* kv = g_kinv[bn];
        kv[0] = (e * i - f * h) * id;  kv[1] = (c * h - b * i) * id;  kv[2] = (b * f - c * e) * id;
        kv[3] = (f * g - d * i) * id;  kv[4] = (a * i - c * g) * id;  kv[5] = (c * d - a * f) * id;
        kv[6] = (d * h - e * g) * id;  kv[7] = (b * g - a * h) * id;  kv[8] = (a * e - b * d) * id;
    }

    // Exactly one float4 per thread: 256 threads * 4 = 1024 = HWQ/CHUNKS elems
    const float4 v = reinterpret_cast<const float4*>(feat + (size_t)row * HWQ)
                     [chunk * F4_PER_CHUNK + tid];
    float sum = __expf(v.x) + __expf(v.y) + __expf(v.z) + __expf(v.w);

    #pragma unroll
    for (int o = 16; o > 0; o >>= 1) sum += __shfl_xor_sync(0xFFFFFFFFu, sum, o);

    __shared__ float sw[8];
    if ((tid & 31) == 0) sw[tid >> 5] = sum;
    __syncthreads();
    if (tid == 0) {
        float t = 0.0f;
        #pragma unroll
        for (int w = 0; w < 8; w++) t += sw[w];
        g_partial[row][chunk] = t;
    }
}

// ---------------------------------------------------------------------------
// Kernel 2 (consumer, PDL): R7-best structure — 64 pixels/block, 2112 blocks.
// Independent preamble (feat loads + exp + consts) runs BEFORE
// griddepcontrol.wait, overlapping the stats kernel's execution.
// ---------------------------------------------------------------------------
__global__ __launch_bounds__(256) void lss_main_kernel(
    const float* __restrict__ feat,      // (BN, C, HW)
    const float* __restrict__ extr,      // (B, N, 4, 4)
    const float* __restrict__ depths,    // (D)
    float* __restrict__ out)             // (BN, 3, HW, D)
{
    const int bn  = blockIdx.y;
    const int tid = threadIdx.x;
    const int p0  = blockIdx.x * 64;

    __shared__ float sS[3][64];
    __shared__ float sE[12];
    __shared__ float sInv[3];

    // ---- Independent preamble (no stats dependency) ----
    float e0 = 0.f, e1 = 0.f, e2 = 0.f, x = 0.f, y = 0.f;
    if (tid < 64) {
        const int p = p0 + tid;
        x = (float)(p % WQ);
        y = (float)(p / WQ);
        const size_t fbase = (size_t)bn * CQ * HWQ + p;
        e0 = __expf(feat[fbase          ]);
        e1 = __expf(feat[fbase +     HWQ]);
        e2 = __expf(feat[fbase + 2 * HWQ]);
    }
    if (tid < 12) sE[tid] = extr[bn * 16 + tid];

    const int q   = tid & 15;            // depth-quad index, fixed per thread
    const int wpl = tid >> 4;            // pixel sub-index 0..15
    const float4 dep = reinterpret_cast<const float4*>(depths)[q];

    // ---- Wait for the stats kernel's results to be visible ----
    asm volatile("griddepcontrol.wait;" ::: "memory");

    // Reduce the 11 partials per row: 3 warps, 11 active lanes each
    if (tid < 96) {
        const int r    = tid >> 5;       // row within bn: warp index 0..2
        const int lane = tid & 31;
        float v = (lane < CHUNKS) ? g_partial[bn * CQ + r][lane] : 0.0f;
        #pragma unroll
        for (int o = 16; o > 0; o >>= 1) v += __shfl_xor_sync(0xFFFFFFFFu, v, o);
        if (lane == 0) sInv[r] = 1.0f / v;
    }
    __syncthreads();

    if (tid < 64) {
        const float* kv = g_kinv[bn];   // uniform loads, L1-resident
        const float t0 = e0 * sInv[0] * fmaf(kv[0], x, fmaf(kv[1], y, kv[2]));
        const float t1 = e1 * sInv[1] * fmaf(kv[3], x, fmaf(kv[4], y, kv[5]));
        const float t2 = e2 * sInv[2] * fmaf(kv[6], x, fmaf(kv[7], y, kv[8]));
        #pragma unroll
        for (int i = 0; i < 3; i++)
            sS[i][tid] = fmaf(sE[i * 4 + 0], t0,
                         fmaf(sE[i * 4 + 1], t1,
                              sE[i * 4 + 2] * t2));
    }
    __syncthreads();

    // ---- Stores: q fixed per thread -> warp spans 512B contiguous ----
    float4* out4 = reinterpret_cast<float4*>(out);
    #pragma unroll
    for (int i = 0; i < 3; i++) {
        const float e3 = sE[i * 4 + 3];
        const size_t base = ((size_t)(bn * 3 + i) * HWQ + p0) * (DQ / 4) + q;
        #pragma unroll
        for (int r = 0; r < 4; r++) {
            const int pl = r * 16 + wpl;
            const float s = sS[i][pl];
            float4 o;
            o.x = fmaf(s, dep.x, e3);
            o.y = fmaf(s, dep.y, e3);
            o.z = fmaf(s, dep.z, e3);
            o.w = fmaf(s, dep.w, e3);
            out4[base + (size_t)pl * (DQ / 4)] = o;
        }
    }
}

extern "C" void kernel_launch(void* const* d_in, const int* in_sizes, int n_in,
                              void* d_out, int out_size)
{
    const float* feat   = (const float*)d_in[0];  // image_features (BN,C,H,W)
    const float* intr   = (const float*)d_in[1];  // intrinsics (B,N,4,4)
    const float* extr   = (const float*)d_in[2];  // extrinsics (B,N,4,4)
    // d_in[3] = xy1 (unused: x,y recomputed exactly from pixel index)
    const float* depths = (const float*)d_in[4];  // (D)
    float* out = (float*)d_out;

    dim3 sgrid(CHUNKS, ROWS);
    lss_stats_kernel<<<sgrid, 256>>>(feat, intr);

    // Main kernel with programmatic dependent launch: overlaps its preamble
    // with the stats kernel; griddepcontrol.wait enforces the data dependency.
    cudaLaunchConfig_t cfg = {};
    cfg.gridDim  = dim3(HWQ / 64, BN);
    cfg.blockDim = dim3(256, 1, 1);
    cfg.dynamicSmemBytes = 0;
    cfg.stream = 0;
    cudaLaunchAttribute attr[1];
    attr[0].id = cudaLaunchAttributeProgrammaticStreamSerialization;
    attr[0].val.programmaticStreamSerializationAllowed = 1;
    cfg.attrs = attr;
    cfg.numAttrs = 1;
    cudaLaunchKernelEx(&cfg, lss_main_kernel, feat, extr, depths, out);
}